// round 16
// baseline (speedup 1.0000x reference)
#include <cuda_runtime.h>
#include <cuda_bf16.h>
#include <mma.h>
#include <cstdint>
#include <cstring>

using namespace nvcuda;

#define BATCH 32768
#define DIN   768
#define HID   3840
#define TOPK  64
#define NSEL  80
#define CAP   512
#define T0FILT 1.55f
#define GAPEPS 1e-4f
#define BANDCAP 32
#define TKT 256   // topk threads

// ---------------- scratch ----------------
__device__ float g_wdecT[(size_t)HID * DIN];
__device__ int   g_cnt[BATCH];
__device__ float g_cval[(size_t)BATCH * CAP];
__device__ int   g_cidx[(size_t)BATCH * CAP];
__device__ __align__(16) __nv_bfloat16 g_xb[(size_t)BATCH * DIN];
__device__ __align__(16) __nv_bfloat16 g_wb[(size_t)HID * DIN];

// ======================= misc =======================
__global__ void zero_cnt_kernel() {
    const int i = blockIdx.x * 1024 + threadIdx.x;
    if (i < BATCH) g_cnt[i] = 0;
}

// ======================= bf16 conversion kernels =======================
__global__ void __launch_bounds__(192) conv_x_kernel(const float* __restrict__ x,
                                                     const float* __restrict__ b_pre) {
    const int row = blockIdx.x;
    const int c4 = threadIdx.x;
    const float4 xv = ((const float4*)(x + (size_t)row * DIN))[c4];
    const float4 bp = ((const float4*)b_pre)[c4];
    __nv_bfloat16 h0 = __float2bfloat16(xv.x - bp.x);
    __nv_bfloat16 h1 = __float2bfloat16(xv.y - bp.y);
    __nv_bfloat16 h2 = __float2bfloat16(xv.z - bp.z);
    __nv_bfloat16 h3 = __float2bfloat16(xv.w - bp.w);
    uint2 p;
    p.x = (uint32_t)*(unsigned short*)&h0 | ((uint32_t)*(unsigned short*)&h1 << 16);
    p.y = (uint32_t)*(unsigned short*)&h2 | ((uint32_t)*(unsigned short*)&h3 << 16);
    ((uint2*)(g_xb + (size_t)row * DIN))[c4] = p;
}

__global__ void __launch_bounds__(192) conv_w_kernel(const float* __restrict__ W) {
    const int row = blockIdx.x;
    const int c4 = threadIdx.x;
    const float4 wv = ((const float4*)(W + (size_t)row * DIN))[c4];
    __nv_bfloat16 h0 = __float2bfloat16(wv.x);
    __nv_bfloat16 h1 = __float2bfloat16(wv.y);
    __nv_bfloat16 h2 = __float2bfloat16(wv.z);
    __nv_bfloat16 h3 = __float2bfloat16(wv.w);
    uint2 p;
    p.x = (uint32_t)*(unsigned short*)&h0 | ((uint32_t)*(unsigned short*)&h1 << 16);
    p.y = (uint32_t)*(unsigned short*)&h2 | ((uint32_t)*(unsigned short*)&h3 << 16);
    ((uint2*)(g_wb + (size_t)row * DIN))[c4] = p;
}

// ======================= WMMA bf16 screening GEMM + fused candidate extraction =======================
#define GBM 128
#define GBN 128
#define GBK 32
#define LDSB 40
#define BUF_ELEMS (GBM * LDSB)
#define GSMEM_BYTES (4 * BUF_ELEMS * 2)

__global__ void __launch_bounds__(256, 2) enc_gemm_wmma(const float* __restrict__ b_enc) {
    extern __shared__ char gsm[];
    __nv_bfloat16* Abuf = (__nv_bfloat16*)gsm;
    __nv_bfloat16* Bbuf = (__nv_bfloat16*)(gsm + 2 * BUF_ELEMS * 2);
    float* stage = (float*)gsm;

    const int bm = blockIdx.y * GBM;
    const int bn = blockIdx.x * GBN;
    const int tid = threadIdx.x, lane = tid & 31, wid = tid >> 5;
    const int wm = wid & 3;
    const int wn = wid >> 2;

    wmma::fragment<wmma::accumulator, 16, 16, 16, float> c[2][4];
    #pragma unroll
    for (int i = 0; i < 2; ++i)
        #pragma unroll
        for (int j = 0; j < 4; ++j) wmma::fill_fragment(c[i][j], 0.f);

    uint4 ra[2], rb[2];
    #pragma unroll
    for (int i = 0; i < 2; ++i) {
        const int idx = tid + 256 * i;
        const int r = idx >> 2, seg = idx & 3;
        ra[i] = *(const uint4*)(g_xb + (size_t)(bm + r) * DIN + seg * 8);
        rb[i] = *(const uint4*)(g_wb + (size_t)(bn + r) * DIN + seg * 8);
    }
    #pragma unroll
    for (int i = 0; i < 2; ++i) {
        const int idx = tid + 256 * i;
        const int r = idx >> 2, seg = idx & 3;
        *(uint4*)(Abuf + r * LDSB + seg * 8) = ra[i];
        *(uint4*)(Bbuf + r * LDSB + seg * 8) = rb[i];
    }
    __syncthreads();

    int buf = 0;
    const int NS = DIN / GBK;

    #pragma unroll 1
    for (int s = 0; s < NS; ++s) {
        const bool has_next = (s + 1 < NS);
        if (has_next) {
            const int k0 = (s + 1) * GBK;
            #pragma unroll
            for (int i = 0; i < 2; ++i) {
                const int idx = tid + 256 * i;
                const int r = idx >> 2, seg = idx & 3;
                ra[i] = *(const uint4*)(g_xb + (size_t)(bm + r) * DIN + k0 + seg * 8);
                rb[i] = *(const uint4*)(g_wb + (size_t)(bn + r) * DIN + k0 + seg * 8);
            }
        }

        const __nv_bfloat16* Ab = Abuf + buf * BUF_ELEMS;
        const __nv_bfloat16* Bb = Bbuf + buf * BUF_ELEMS;
        #pragma unroll
        for (int ks = 0; ks < 2; ++ks) {
            wmma::fragment<wmma::matrix_a, 16, 16, 16, __nv_bfloat16, wmma::row_major> af[2];
            wmma::fragment<wmma::matrix_b, 16, 16, 16, __nv_bfloat16, wmma::col_major> bfr[4];
            #pragma unroll
            for (int i = 0; i < 2; ++i)
                wmma::load_matrix_sync(af[i], Ab + (wm * 32 + 16 * i) * LDSB + ks * 16, LDSB);
            #pragma unroll
            for (int j = 0; j < 4; ++j)
                wmma::load_matrix_sync(bfr[j], Bb + (wn * 64 + 16 * j) * LDSB + ks * 16, LDSB);
            #pragma unroll
            for (int i = 0; i < 2; ++i)
                #pragma unroll
                for (int j = 0; j < 4; ++j)
                    wmma::mma_sync(c[i][j], af[i], bfr[j], c[i][j]);
        }

        if (has_next) {
            const int nb = buf ^ 1;
            #pragma unroll
            for (int i = 0; i < 2; ++i) {
                const int idx = tid + 256 * i;
                const int r = idx >> 2, seg = idx & 3;
                *(uint4*)(Abuf + nb * BUF_ELEMS + r * LDSB + seg * 8) = ra[i];
                *(uint4*)(Bbuf + nb * BUF_ELEMS + r * LDSB + seg * 8) = rb[i];
            }
        }
        __syncthreads();
        buf ^= 1;
    }

    // epilogue: stage frags, add b_enc, push candidates > T0FILT (no dense h store)
    float* wstage = stage + wid * 320;
    const int rr = lane >> 1;
    const int cc = (lane & 1) * 8;
    #pragma unroll
    for (int i = 0; i < 2; ++i) {
        #pragma unroll
        for (int j = 0; j < 4; ++j) {
            wmma::store_matrix_sync(wstage, c[i][j], 20, wmma::mem_row_major);
            __syncwarp();
            const int m = bm + wm * 32 + 16 * i + rr;
            const int n = bn + wn * 64 + 16 * j + cc;
            float4 v0 = *(float4*)(wstage + rr * 20 + cc);
            float4 v1 = *(float4*)(wstage + rr * 20 + cc + 4);
            const float4 be0 = *(const float4*)(b_enc + n);
            const float4 be1 = *(const float4*)(b_enc + n + 4);
            float vals[8];
            vals[0] = v0.x + be0.x; vals[1] = v0.y + be0.y;
            vals[2] = v0.z + be0.z; vals[3] = v0.w + be0.w;
            vals[4] = v1.x + be1.x; vals[5] = v1.y + be1.y;
            vals[6] = v1.z + be1.z; vals[7] = v1.w + be1.w;
            #pragma unroll
            for (int e = 0; e < 8; ++e) {
                if (vals[e] > T0FILT) {
                    int p = atomicAdd(&g_cnt[m], 1);
                    if (p < CAP) {
                        g_cval[(size_t)m * CAP + p] = vals[e];
                        g_cidx[(size_t)m * CAP + p] = n + e;
                    }
                }
            }
            __syncwarp();
        }
    }
}

// ======================= W_dec [D,H] -> W_decT [H,D] =======================
__global__ void transpose_kernel(const float* __restrict__ in)
{
    __shared__ float t[32][33];
    const int bx = blockIdx.x * 32;
    const int by = blockIdx.y * 32;
    const int x = bx + threadIdx.x;
    #pragma unroll
    for (int j = 0; j < 32; j += 8)
        t[threadIdx.y + j][threadIdx.x] = in[(size_t)(by + threadIdx.y + j) * HID + x];
    __syncthreads();
    const int x2 = by + threadIdx.x;
    #pragma unroll
    for (int j = 0; j < 32; j += 8)
        g_wdecT[(size_t)(bx + threadIdx.y + j) * DIN + x2] = t[threadIdx.x][threadIdx.y + j];
}

// ---- one-candidate fp32 dot helper (warp-strided, 6 independent LDG.128) ----
__device__ __forceinline__ float dot_row(const float4* __restrict__ wr4,
                                         const float4* __restrict__ xc4, int lane) {
    float4 w[6], xv[6];
    #pragma unroll
    for (int u = 0; u < 6; ++u) w[u] = wr4[lane + 32 * u];
    #pragma unroll
    for (int u = 0; u < 6; ++u) xv[u] = xc4[lane + 32 * u];
    float s = 0.f;
    #pragma unroll
    for (int u = 0; u < 6; ++u) {
        s = fmaf(xv[u].x, w[u].x, s);
        s = fmaf(xv[u].y, w[u].y, s);
        s = fmaf(xv[u].z, w[u].z, s);
        s = fmaf(xv[u].w, w[u].w, s);
    }
    return s;
}

// ======================= topk + fused decoder =======================
__global__ void __launch_bounds__(TKT) topk_kernel(
    float* __restrict__ h_sparse, float* __restrict__ xrec,
    const float* __restrict__ x, const float* __restrict__ W_enc,
    const float* __restrict__ b_pre, const float* __restrict__ b_enc)
{
    const int row = blockIdx.x;
    __shared__ float xc[DIN];
    __shared__ float hv[HID];       // fallback-only full row
    __shared__ float cv[CAP];
    __shared__ int   ci[CAP];
    __shared__ int   s_nsel, s_nband, s_doband;
    __shared__ int   sel_i[NSEL];
    __shared__ float s_val[NSEL];
    __shared__ int   s_rank[NSEL];
    __shared__ unsigned char s_member[NSEL];
    __shared__ float s_v63, s_v64;
    __shared__ int   bnd_sl[BANDCAP];
    __shared__ float bnd_sv[BANDCAP];
    __shared__ int   out_i[TOPK];
    __shared__ float out_v[TOPK];

    const int tid = threadIdx.x, lane = tid & 31, wrp = tid >> 5;

    if (tid == 0) { s_nband = 0; s_doband = 0; s_v63 = 3.0e38f; s_v64 = -3.0e38f; }

    // exact centered x row into smem
    {
        const float4* x4 = (const float4*)(x + (size_t)row * DIN);
        const float4* b4 = (const float4*)b_pre;
        for (int i = tid; i < DIN / 4; i += TKT) {
            float4 xv = x4[i], bp = b4[i];
            xv.x -= bp.x; xv.y -= bp.y; xv.z -= bp.z; xv.w -= bp.w;
            ((float4*)xc)[i] = xv;
        }
    }
    __syncthreads();

    const int cnt = g_cnt[row];
    const bool fb = (cnt < TOPK) || (cnt > CAP);

    if (!fb) {
        // load candidate list from global
        for (int i = tid; i < cnt; i += TKT) {
            cv[i] = g_cval[(size_t)row * CAP + i];
            ci[i] = g_cidx[(size_t)row * CAP + i];
        }
        __syncthreads();
        if (cnt <= NSEL) {
            if (tid == 0) s_nsel = cnt;
            if (tid < cnt) sel_i[tid] = ci[tid];
        } else {
            if (tid == 0) s_nsel = NSEL;
            for (int c = tid; c < cnt; c += TKT) {
                const float mv = cv[c];
                const int mi = ci[c];
                int rank = 0;
                for (int m = 0; m < cnt; ++m) {
                    const float ov = cv[m];
                    if (ov > mv || (ov == mv && ci[m] < mi)) ++rank;
                }
                if (rank < NSEL) sel_i[rank] = mi;
            }
        }
    } else {
        // never-path: recompute the full row, counting-rank top-NSEL over all HID
        if (tid == 0) s_nsel = NSEL;
        const float4* xc4 = (const float4*)xc;
        for (int j = wrp; j < HID; j += TKT / 32) {
            float s = dot_row((const float4*)(W_enc + (size_t)j * DIN), xc4, lane);
            #pragma unroll
            for (int o = 16; o > 0; o >>= 1) s += __shfl_xor_sync(0xffffffffu, s, o);
            if (lane == 0) hv[j] = s + b_enc[j];
        }
        __syncthreads();
        for (int j = tid; j < HID; j += TKT) {
            const float mv = hv[j];
            int rank = 0;
            for (int m = 0; m < HID; ++m) {
                const float ov = hv[m];
                if (ov > mv || (ov == mv && m < j)) ++rank;
            }
            if (rank < NSEL) sel_i[rank] = j;
        }
    }
    __syncthreads();
    const int nsel = s_nsel;

    // fp32 warp-parallel rescore, 2 candidates per pass
    {
        const float4* xc4 = (const float4*)xc;
        #pragma unroll 1
        for (int q0 = 0; q0 < NSEL / 8; q0 += 2) {
            const int sl0 = wrp * (NSEL / 8) + q0;
            const int sl1 = sl0 + 1;
            const bool a0 = (sl0 < nsel), a1 = (sl1 < nsel);
            const int j0 = a0 ? sel_i[sl0] : 0;
            const int j1 = a1 ? sel_i[sl1] : 0;
            float s0 = a0 ? dot_row((const float4*)(W_enc + (size_t)j0 * DIN), xc4, lane) : 0.f;
            float s1 = a1 ? dot_row((const float4*)(W_enc + (size_t)j1 * DIN), xc4, lane) : 0.f;
            #pragma unroll
            for (int o = 16; o > 0; o >>= 1) {
                s0 += __shfl_xor_sync(0xffffffffu, s0, o);
                s1 += __shfl_xor_sync(0xffffffffu, s1, o);
            }
            if (lane == 0) {
                if (a0) s_val[sl0] = s0 + b_enc[j0];
                if (a1) s_val[sl1] = s1 + b_enc[j1];
            }
        }
    }
    __syncthreads();

    // rank by value (desc, idx asc); default membership = rank < 64
    if (tid < nsel) {
        const float mv = s_val[tid];
        const int mi = sel_i[tid];
        int rank = 0;
        for (int m = 0; m < nsel; ++m) {
            const float ov = s_val[m];
            const int oi = sel_i[m];
            if (ov > mv || (ov == mv && oi < mi)) ++rank;
        }
        s_rank[tid] = rank;
        s_member[tid] = (rank < TOPK) ? 1 : 0;
        if (rank == TOPK - 1) s_v63 = mv;
        if (rank == TOPK)     s_v64 = mv;
    }
    __syncthreads();

    if (tid == 0 && nsel > TOPK && (s_v63 - s_v64) < GAPEPS) s_doband = 1;
    __syncthreads();

    if (s_doband) {
        if (tid < nsel) {
            const float v = s_val[tid];
            if (v >= s_v64 - GAPEPS && v <= s_v63 + GAPEPS) {
                int p = atomicAdd(&s_nband, 1);
                if (p < BANDCAP) bnd_sl[p] = tid;
            }
        }
        __syncthreads();
        const int nb = min(s_nband, BANDCAP);
        // serial fp32 k-ascending rescore of band members (jax-matching, R12-R15 verified)
        if (tid < nb) {
            const int sl = bnd_sl[tid];
            const int j = sel_i[sl];
            const float* wr = W_enc + (size_t)j * DIN;
            float acc = 0.f;
            #pragma unroll 8
            for (int k = 0; k < DIN; ++k)
                acc = fmaf(xc[k], wr[k], acc);
            bnd_sv[tid] = acc + b_enc[j];
        }
        __syncthreads();
        if (tid == 0) {
            int slots = 0;
            for (int m = 0; m < nb; ++m) {
                if (s_rank[bnd_sl[m]] < TOPK) ++slots;
                s_member[bnd_sl[m]] = 0;
            }
            bool used[BANDCAP];
            for (int m = 0; m < nb; ++m) used[m] = false;
            for (int s = 0; s < slots; ++s) {
                int best = -1;
                for (int m = 0; m < nb; ++m) {
                    if (used[m]) continue;
                    if (best < 0 || bnd_sv[m] > bnd_sv[best] ||
                        (bnd_sv[m] == bnd_sv[best] && sel_i[bnd_sl[m]] < sel_i[bnd_sl[best]])) best = m;
                }
                used[best] = true;
                s_member[bnd_sl[best]] = 1;
            }
        }
        __syncthreads();
    }

    // deterministic compaction (prefix count)
    if (tid < nsel && s_member[tid]) {
        int pos = 0;
        for (int m = 0; m < tid; ++m) pos += s_member[m];
        const float fv = s_val[tid];
        out_i[pos] = sel_i[tid];
        out_v[pos] = fv > 0.f ? fv : 0.f;
    }
    __syncthreads();

    // scatter h_sparse
    float* orow = h_sparse + (size_t)row * HID;
    const float4 z4 = make_float4(0.f, 0.f, 0.f, 0.f);
    for (int i = tid; i < HID / 4; i += TKT) ((float4*)orow)[i] = z4;
    __syncthreads();
    if (tid < TOPK) orow[out_i[tid]] = out_v[tid];

    // fused decoder: x_rec[row] = sum_k out_v[k] * W_decT[out_i[k], :] + b_pre
    if (tid < 192) {
        float4 acc = ((const float4*)b_pre)[tid];
        #pragma unroll 4
        for (int k = 0; k < TOPK; ++k) {
            const float v = out_v[k];
            const float4 wv = ((const float4*)(g_wdecT + (size_t)out_i[k] * DIN))[tid];
            acc.x = fmaf(v, wv.x, acc.x);
            acc.y = fmaf(v, wv.y, acc.y);
            acc.z = fmaf(v, wv.z, acc.z);
            acc.w = fmaf(v, wv.w, acc.w);
        }
        ((float4*)(xrec + (size_t)row * DIN))[tid] = acc;
    }
}

// ======================= launch =======================
extern "C" void kernel_launch(void* const* d_in, const int* in_sizes, int n_in,
                              void* d_out, int out_size)
{
    const float* x     = (const float*)d_in[0];
    const float* W_enc = (const float*)d_in[1];
    const float* b_enc = (const float*)d_in[2];
    const float* W_dec = (const float*)d_in[3];
    const float* b_pre = (const float*)d_in[4];

    float* out      = (float*)d_out;
    float* xrec     = out;                        // [B, 768]
    float* h_sparse = out + (size_t)BATCH * DIN;  // [B, 3840]

    cudaFuncSetAttribute(enc_gemm_wmma, cudaFuncAttributeMaxDynamicSharedMemorySize, GSMEM_BYTES);

    zero_cnt_kernel<<<32, 1024>>>();
    conv_x_kernel<<<BATCH, 192>>>(x, b_pre);
    conv_w_kernel<<<HID, 192>>>(W_enc);
    transpose_kernel<<<dim3(HID / 32, DIN / 32), dim3(32, 8)>>>(W_dec);

    enc_gemm_wmma<<<dim3(HID / GBN, BATCH / GBM), 256, GSMEM_BYTES>>>(b_enc);

    topk_kernel<<<BATCH, TKT>>>(h_sparse, xrec, x, W_enc, b_pre, b_enc);
}

// round 17
// speedup vs baseline: 1.1037x; 1.1037x over previous
#include <cuda_runtime.h>
#include <cuda_bf16.h>
#include <mma.h>
#include <cstdint>
#include <cstring>

using namespace nvcuda;

#define BATCH 32768
#define DIN   768
#define HID   3840
#define TOPK  64
#define NSEL  80
#define CAP   512
#define T0FILT 1.55f
#define GAPEPS 1e-4f
#define BANDCAP 32
#define TKT 256

// ---------------- scratch ----------------
__device__ float g_wdecT[(size_t)HID * DIN];
__device__ int   g_cnt[BATCH];
__device__ __align__(16) uint2 g_cpair[(size_t)BATCH * CAP];  // {val bits, idx}
__device__ __align__(16) __nv_bfloat16 g_xb[(size_t)BATCH * DIN];
__device__ __align__(16) __nv_bfloat16 g_wb[(size_t)HID * DIN];

// ======================= misc =======================
__global__ void zero_cnt_kernel() {
    const int i = blockIdx.x * 1024 + threadIdx.x;
    if (i < BATCH) g_cnt[i] = 0;
}

__device__ __forceinline__ void cpa16(uint32_t s, const void* g) {
    asm volatile("{ .reg .u64 gg; cvta.to.global.u64 gg, %1; cp.async.cg.shared.global [%0], [gg], 16; }"
                 :: "r"(s), "l"(g));
}
#define CP_COMMIT() asm volatile("cp.async.commit_group;" ::: "memory")
#define CP_WAIT(n)  asm volatile("cp.async.wait_group %0;" :: "n"(n) : "memory")

__device__ __forceinline__ uint32_t smem_u32(const void* p) {
    uint32_t a;
    asm("{ .reg .u64 t; cvta.to.shared.u64 t, %1; cvt.u32.u64 %0, t; }" : "=r"(a) : "l"(p));
    return a;
}

// ======================= bf16 conversion kernels =======================
__global__ void __launch_bounds__(192) conv_x_kernel(const float* __restrict__ x,
                                                     const float* __restrict__ b_pre) {
    const int row = blockIdx.x;
    const int c4 = threadIdx.x;
    const float4 xv = ((const float4*)(x + (size_t)row * DIN))[c4];
    const float4 bp = ((const float4*)b_pre)[c4];
    __nv_bfloat16 h0 = __float2bfloat16(xv.x - bp.x);
    __nv_bfloat16 h1 = __float2bfloat16(xv.y - bp.y);
    __nv_bfloat16 h2 = __float2bfloat16(xv.z - bp.z);
    __nv_bfloat16 h3 = __float2bfloat16(xv.w - bp.w);
    uint2 p;
    p.x = (uint32_t)*(unsigned short*)&h0 | ((uint32_t)*(unsigned short*)&h1 << 16);
    p.y = (uint32_t)*(unsigned short*)&h2 | ((uint32_t)*(unsigned short*)&h3 << 16);
    ((uint2*)(g_xb + (size_t)row * DIN))[c4] = p;
}

__global__ void __launch_bounds__(192) conv_w_kernel(const float* __restrict__ W) {
    const int row = blockIdx.x;
    const int c4 = threadIdx.x;
    const float4 wv = ((const float4*)(W + (size_t)row * DIN))[c4];
    __nv_bfloat16 h0 = __float2bfloat16(wv.x);
    __nv_bfloat16 h1 = __float2bfloat16(wv.y);
    __nv_bfloat16 h2 = __float2bfloat16(wv.z);
    __nv_bfloat16 h3 = __float2bfloat16(wv.w);
    uint2 p;
    p.x = (uint32_t)*(unsigned short*)&h0 | ((uint32_t)*(unsigned short*)&h1 << 16);
    p.y = (uint32_t)*(unsigned short*)&h2 | ((uint32_t)*(unsigned short*)&h3 << 16);
    ((uint2*)(g_wb + (size_t)row * DIN))[c4] = p;
}

// ======================= WMMA bf16 GEMM: cp.async 3-stage + fused candidate extraction =======================
#define GBM 128
#define GBN 128
#define GBK 32
#define LDSB 40                        // bf16 per smem row (32 + 8 pad = 80 B)
#define ROWB2 (LDSB * 2)               // 80 bytes
#define A_BYTES (GBM * ROWB2)          // 10240
#define STG_BYTES (2 * A_BYTES)        // A + B = 20480
#define NSTG 3
#define GSMEM_BYTES (NSTG * STG_BYTES) // 61440

__global__ void __launch_bounds__(256) enc_gemm_wmma(const float* __restrict__ b_enc) {
    extern __shared__ char gsm[];
    const uint32_t sb = smem_u32(gsm);

    const int bm = blockIdx.y * GBM;
    const int bn = blockIdx.x * GBN;
    const int tid = threadIdx.x, lane = tid & 31, wid = tid >> 5;
    const int wm = wid & 3;
    const int wn = wid >> 2;

    // load indices: A 512 chunks, B 512 chunks; 2 each per thread
    const int lr0 = tid >> 1;                 // 0..127 (A row for i=0... see below)
    // use idx scheme: idx = tid + 256*i; r = idx>>2; seg = idx&3

    wmma::fragment<wmma::accumulator, 16, 16, 16, float> c[2][4];
    #pragma unroll
    for (int i = 0; i < 2; ++i)
        #pragma unroll
        for (int j = 0; j < 4; ++j) wmma::fill_fragment(c[i][j], 0.f);

    const int NS = DIN / GBK;  // 24

    // prologue: stages 0,1
    #pragma unroll
    for (int s = 0; s < 2; ++s) {
        const uint32_t st = sb + s * STG_BYTES;
        const int k0 = s * GBK;
        #pragma unroll
        for (int i = 0; i < 2; ++i) {
            const int idx = tid + 256 * i;
            const int r = idx >> 2, seg = idx & 3;
            cpa16(st + r * ROWB2 + seg * 16,
                  g_xb + (size_t)(bm + r) * DIN + k0 + seg * 8);
            cpa16(st + A_BYTES + r * ROWB2 + seg * 16,
                  g_wb + (size_t)(bn + r) * DIN + k0 + seg * 8);
        }
        CP_COMMIT();
    }

    #pragma unroll 1
    for (int s = 0; s < NS; ++s) {
        CP_WAIT(1);
        __syncthreads();

        if (s + 2 < NS) {
            const uint32_t st = sb + ((s + 2) % NSTG) * STG_BYTES;
            const int k0 = (s + 2) * GBK;
            #pragma unroll
            for (int i = 0; i < 2; ++i) {
                const int idx = tid + 256 * i;
                const int r = idx >> 2, seg = idx & 3;
                cpa16(st + r * ROWB2 + seg * 16,
                      g_xb + (size_t)(bm + r) * DIN + k0 + seg * 8);
                cpa16(st + A_BYTES + r * ROWB2 + seg * 16,
                      g_wb + (size_t)(bn + r) * DIN + k0 + seg * 8);
            }
        }
        CP_COMMIT();

        const __nv_bfloat16* Ab = (const __nv_bfloat16*)(gsm + (s % NSTG) * STG_BYTES);
        const __nv_bfloat16* Bb = (const __nv_bfloat16*)(gsm + (s % NSTG) * STG_BYTES + A_BYTES);
        #pragma unroll
        for (int ks = 0; ks < 2; ++ks) {
            wmma::fragment<wmma::matrix_a, 16, 16, 16, __nv_bfloat16, wmma::row_major> af[2];
            wmma::fragment<wmma::matrix_b, 16, 16, 16, __nv_bfloat16, wmma::col_major> bfr[4];
            #pragma unroll
            for (int i = 0; i < 2; ++i)
                wmma::load_matrix_sync(af[i], Ab + (wm * 32 + 16 * i) * LDSB + ks * 16, LDSB);
            #pragma unroll
            for (int j = 0; j < 4; ++j)
                wmma::load_matrix_sync(bfr[j], Bb + (wn * 64 + 16 * j) * LDSB + ks * 16, LDSB);
            #pragma unroll
            for (int i = 0; i < 2; ++i)
                #pragma unroll
                for (int j = 0; j < 4; ++j)
                    wmma::mma_sync(c[i][j], af[i], bfr[j], c[i][j]);
        }
    }
    __syncthreads();

    // epilogue: stage frags through smem (aliased), add b_enc, push candidates (aggregated)
    float* stage = (float*)gsm;
    float* wstage = stage + wid * 320;  // 16 rows x 20 floats
    const int rr = lane >> 1;
    const int cc = (lane & 1) * 8;
    #pragma unroll
    for (int i = 0; i < 2; ++i) {
        #pragma unroll
        for (int j = 0; j < 4; ++j) {
            wmma::store_matrix_sync(wstage, c[i][j], 20, wmma::mem_row_major);
            __syncwarp();
            const int m = bm + wm * 32 + 16 * i + rr;
            const int n = bn + wn * 64 + 16 * j + cc;
            float4 v0 = *(float4*)(wstage + rr * 20 + cc);
            float4 v1 = *(float4*)(wstage + rr * 20 + cc + 4);
            const float4 be0 = *(const float4*)(b_enc + n);
            const float4 be1 = *(const float4*)(b_enc + n + 4);
            float vals[8];
            vals[0] = v0.x + be0.x; vals[1] = v0.y + be0.y;
            vals[2] = v0.z + be0.z; vals[3] = v0.w + be0.w;
            vals[4] = v1.x + be1.x; vals[5] = v1.y + be1.y;
            vals[6] = v1.z + be1.z; vals[7] = v1.w + be1.w;
            // aggregate: one atomic per thread per frag
            uint2 loc[8];
            int nl = 0;
            #pragma unroll
            for (int e = 0; e < 8; ++e) {
                if (vals[e] > T0FILT) {
                    loc[nl].x = __float_as_uint(vals[e]);
                    loc[nl].y = (uint32_t)(n + e);
                    ++nl;
                }
            }
            if (nl) {
                int p = atomicAdd(&g_cnt[m], nl);
                for (int e = 0; e < nl && p + e < CAP; ++e)
                    g_cpair[(size_t)m * CAP + p + e] = loc[e];
            }
            __syncwarp();
        }
    }
}

// ======================= W_dec [D,H] -> W_decT [H,D] =======================
__global__ void transpose_kernel(const float* __restrict__ in)
{
    __shared__ float t[32][33];
    const int bx = blockIdx.x * 32;
    const int by = blockIdx.y * 32;
    const int x = bx + threadIdx.x;
    #pragma unroll
    for (int j = 0; j < 32; j += 8)
        t[threadIdx.y + j][threadIdx.x] = in[(size_t)(by + threadIdx.y + j) * HID + x];
    __syncthreads();
    const int x2 = by + threadIdx.x;
    #pragma unroll
    for (int j = 0; j < 32; j += 8)
        g_wdecT[(size_t)(bx + threadIdx.y + j) * DIN + x2] = t[threadIdx.x][threadIdx.y + j];
}

// ---- one-candidate fp32 dot (warp-strided, 6 independent LDG.128) ----
__device__ __forceinline__ float dot_row(const float4* __restrict__ wr4,
                                         const float4* __restrict__ xc4, int lane) {
    float4 w[6], xv[6];
    #pragma unroll
    for (int u = 0; u < 6; ++u) w[u] = wr4[lane + 32 * u];
    #pragma unroll
    for (int u = 0; u < 6; ++u) xv[u] = xc4[lane + 32 * u];
    float s = 0.f;
    #pragma unroll
    for (int u = 0; u < 6; ++u) {
        s = fmaf(xv[u].x, w[u].x, s);
        s = fmaf(xv[u].y, w[u].y, s);
        s = fmaf(xv[u].z, w[u].z, s);
        s = fmaf(xv[u].w, w[u].w, s);
    }
    return s;
}

// ======================= topk + fused decoder =======================
__global__ void __launch_bounds__(TKT) topk_kernel(
    float* __restrict__ h_sparse, float* __restrict__ xrec,
    const float* __restrict__ x, const float* __restrict__ W_enc,
    const float* __restrict__ b_pre, const float* __restrict__ b_enc)
{
    const int row = blockIdx.x;
    __shared__ float xc[DIN];
    __shared__ float cv[CAP];
    __shared__ int   ci[CAP];
    __shared__ int   s_nsel, s_nband, s_doband;
    __shared__ int   sel_i[NSEL];
    __shared__ float s_val[NSEL];
    __shared__ int   s_rank[NSEL];
    __shared__ unsigned char s_member[NSEL];
    __shared__ float s_v63, s_v64;
    __shared__ int   bnd_sl[BANDCAP];
    __shared__ float bnd_sv[BANDCAP];
    __shared__ int   out_i[TOPK];
    __shared__ float out_v[TOPK];

    const int tid = threadIdx.x, lane = tid & 31, wrp = tid >> 5;
    float* orow = h_sparse + (size_t)row * HID;

    if (tid == 0) { s_nband = 0; s_doband = 0; s_v63 = 3.0e38f; s_v64 = -3.0e38f; }

    // exact centered x row into smem
    {
        const float4* x4 = (const float4*)(x + (size_t)row * DIN);
        const float4* b4 = (const float4*)b_pre;
        for (int i = tid; i < DIN / 4; i += TKT) {
            float4 xv = x4[i], bp = b4[i];
            xv.x -= bp.x; xv.y -= bp.y; xv.z -= bp.z; xv.w -= bp.w;
            ((float4*)xc)[i] = xv;
        }
    }
    __syncthreads();

    const int cnt = g_cnt[row];
    const bool fb = (cnt < TOPK) || (cnt > CAP);

    if (!fb) {
        for (int i = tid; i < cnt; i += TKT) {
            const uint2 pr = g_cpair[(size_t)row * CAP + i];
            cv[i] = __uint_as_float(pr.x);
            ci[i] = (int)pr.y;
        }
        __syncthreads();
        if (cnt <= NSEL) {
            if (tid == 0) s_nsel = cnt;
            if (tid < cnt) sel_i[tid] = ci[tid];
        } else {
            if (tid == 0) s_nsel = NSEL;
            for (int c = tid; c < cnt; c += TKT) {
                const float mv = cv[c];
                const int mi = ci[c];
                int rank = 0;
                for (int m = 0; m < cnt; ++m) {
                    const float ov = cv[m];
                    if (ov > mv || (ov == mv && ci[m] < mi)) ++rank;
                }
                if (rank < NSEL) sel_i[rank] = mi;
            }
        }
    } else {
        // never-path: recompute full row into h_sparse row (scratch; re-zeroed later)
        if (tid == 0) s_nsel = NSEL;
        const float4* xc4 = (const float4*)xc;
        for (int j = wrp; j < HID; j += TKT / 32) {
            float s = dot_row((const float4*)(W_enc + (size_t)j * DIN), xc4, lane);
            #pragma unroll
            for (int o = 16; o > 0; o >>= 1) s += __shfl_xor_sync(0xffffffffu, s, o);
            if (lane == 0) orow[j] = s + b_enc[j];
        }
        __syncthreads();
        for (int j = tid; j < HID; j += TKT) {
            const float mv = orow[j];
            int rank = 0;
            for (int m = 0; m < HID; ++m) {
                const float ov = orow[m];
                if (ov > mv || (ov == mv && m < j)) ++rank;
            }
            if (rank < NSEL) sel_i[rank] = j;
        }
    }
    __syncthreads();
    const int nsel = s_nsel;

    // fp32 warp-parallel rescore, 2 candidates per pass
    {
        const float4* xc4 = (const float4*)xc;
        #pragma unroll 1
        for (int q0 = 0; q0 < NSEL / 8; q0 += 2) {
            const int sl0 = wrp * (NSEL / 8) + q0;
            const int sl1 = sl0 + 1;
            const bool a0 = (sl0 < nsel), a1 = (sl1 < nsel);
            const int j0 = a0 ? sel_i[sl0] : 0;
            const int j1 = a1 ? sel_i[sl1] : 0;
            float s0 = a0 ? dot_row((const float4*)(W_enc + (size_t)j0 * DIN), xc4, lane) : 0.f;
            float s1 = a1 ? dot_row((const float4*)(W_enc + (size_t)j1 * DIN), xc4, lane) : 0.f;
            #pragma unroll
            for (int o = 16; o > 0; o >>= 1) {
                s0 += __shfl_xor_sync(0xffffffffu, s0, o);
                s1 += __shfl_xor_sync(0xffffffffu, s1, o);
            }
            if (lane == 0) {
                if (a0) s_val[sl0] = s0 + b_enc[j0];
                if (a1) s_val[sl1] = s1 + b_enc[j1];
            }
        }
    }
    __syncthreads();

    // rank by value (desc, idx asc)
    if (tid < nsel) {
        const float mv = s_val[tid];
        const int mi = sel_i[tid];
        int rank = 0;
        for (int m = 0; m < nsel; ++m) {
            const float ov = s_val[m];
            const int oi = sel_i[m];
            if (ov > mv || (ov == mv && oi < mi)) ++rank;
        }
        s_rank[tid] = rank;
        s_member[tid] = (rank < TOPK) ? 1 : 0;
        if (rank == TOPK - 1) s_v63 = mv;
        if (rank == TOPK)     s_v64 = mv;
    }
    __syncthreads();

    if (tid == 0 && nsel > TOPK && (s_v63 - s_v64) < GAPEPS) s_doband = 1;
    __syncthreads();

    if (s_doband) {
        if (tid < nsel) {
            const float v = s_val[tid];
            if (v >= s_v64 - GAPEPS && v <= s_v63 + GAPEPS) {
                int p = atomicAdd(&s_nband, 1);
                if (p < BANDCAP) bnd_sl[p] = tid;
            }
        }
        __syncthreads();
        const int nb = min(s_nband, BANDCAP);
        // serial fp32 k-ascending rescore (jax-matching, R12-R16 verified)
        if (tid < nb) {
            const int sl = bnd_sl[tid];
            const int j = sel_i[sl];
            const float* wr = W_enc + (size_t)j * DIN;
            float acc = 0.f;
            #pragma unroll 8
            for (int k = 0; k < DIN; ++k)
                acc = fmaf(xc[k], wr[k], acc);
            bnd_sv[tid] = acc + b_enc[j];
        }
        __syncthreads();
        if (tid == 0) {
            int slots = 0;
            for (int m = 0; m < nb; ++m) {
                if (s_rank[bnd_sl[m]] < TOPK) ++slots;
                s_member[bnd_sl[m]] = 0;
            }
            bool used[BANDCAP];
            for (int m = 0; m < nb; ++m) used[m] = false;
            for (int s = 0; s < slots; ++s) {
                int best = -1;
                for (int m = 0; m < nb; ++m) {
                    if (used[m]) continue;
                    if (best < 0 || bnd_sv[m] > bnd_sv[best] ||
                        (bnd_sv[m] == bnd_sv[best] && sel_i[bnd_sl[m]] < sel_i[bnd_sl[best]])) best = m;
                }
                used[best] = true;
                s_member[bnd_sl[best]] = 1;
            }
        }
        __syncthreads();
    }

    // deterministic compaction
    if (tid < nsel && s_member[tid]) {
        int pos = 0;
        for (int m = 0; m < tid; ++m) pos += s_member[m];
        const float fv = s_val[tid];
        out_i[pos] = sel_i[tid];
        out_v[pos] = fv > 0.f ? fv : 0.f;
    }
    __syncthreads();

    // scatter h_sparse
    const float4 z4 = make_float4(0.f, 0.f, 0.f, 0.f);
    for (int i = tid; i < HID / 4; i += TKT) ((float4*)orow)[i] = z4;
    __syncthreads();
    if (tid < TOPK) orow[out_i[tid]] = out_v[tid];

    // fused decoder
    if (tid < 192) {
        float4 acc = ((const float4*)b_pre)[tid];
        #pragma unroll 4
        for (int k = 0; k < TOPK; ++k) {
            const float v = out_v[k];
            const float4 wv = ((const float4*)(g_wdecT + (size_t)out_i[k] * DIN))[tid];
            acc.x = fmaf(v, wv.x, acc.x);
            acc.y = fmaf(v, wv.y, acc.y);
            acc.z = fmaf(v, wv.z, acc.z);
            acc.w = fmaf(v, wv.w, acc.w);
        }
        ((float4*)(xrec + (size_t)row * DIN))[tid] = acc;
    }
}

// ======================= launch =======================
extern "C" void kernel_launch(void* const* d_in, const int* in_sizes, int n_in,
                              void* d_out, int out_size)
{
    const float* x     = (const float*)d_in[0];
    const float* W_enc = (const float*)d_in[1];
    const float* b_enc = (const float*)d_in[2];
    const float* W_dec = (const float*)d_in[3];
    const float* b_pre = (const float*)d_in[4];

    float* out      = (float*)d_out;
    float* xrec     = out;                        // [B, 768]
    float* h_sparse = out + (size_t)BATCH * DIN;  // [B, 3840]

    cudaFuncSetAttribute(enc_gemm_wmma, cudaFuncAttributeMaxDynamicSharedMemorySize, GSMEM_BYTES);

    zero_cnt_kernel<<<32, 1024>>>();
    conv_x_kernel<<<BATCH, 192>>>(x, b_pre);
    conv_w_kernel<<<HID, 192>>>(W_enc);
    transpose_kernel<<<dim3(HID / 32, DIN / 32), dim3(32, 8)>>>(W_dec);

    enc_gemm_wmma<<<dim3(HID / GBN, BATCH / GBM), 256, GSMEM_BYTES>>>(b_enc);

    topk_kernel<<<BATCH, TKT>>>(h_sparse, xrec, x, W_enc, b_pre, b_enc);
}